// round 7
// baseline (speedup 1.0000x reference)
#include <cuda_runtime.h>

#define NN    4096

#define PED_SPEED   1.5f
#define ROBOT_SPEED 1.5f
#define K_ATTR      2.0f
#define ALPHA       10.0f
#define PED_RADIUS  0.3f
#define PED_MASS    60.0f
#define BETTA       0.71f
#define DT          0.4f
#define A_COST      4.0f
#define B_COST      1.2f
#define E_COST      0.001f
#define EPSF        1e-8f
#define LOG2E       1.4426950408889634f

#define C1C (-LOG2E / BETTA)
#define C0C ((2.0f * PED_RADIUS) * LOG2E / BETTA)

__device__ float4 g_pos4[NN / 2];   // packed positions (32 KB, L1-resident)
__device__ float  g_robo[4];        // r0x, r0y, PG

__device__ __forceinline__ float ex2_approx(float x) {
    float r;
    asm("ex2.approx.ftz.f32 %0, %1;" : "=f"(r) : "f"(x));
    return r;
}
__device__ __forceinline__ float rsqrt_approx(float x) {
    float r;
    asm("rsqrt.approx.ftz.f32 %0, %1;" : "=f"(r) : "f"(x));
    return r;
}

// Prep: blocks 0..7 pack positions; block 8 computes robot (row 0) pose + PG.
__global__ void __launch_bounds__(512) prep_kernel(
    const float4* __restrict__ state,
    const float2* __restrict__ goals,
    const float*  __restrict__ robot_init)
{
    const int tid = threadIdx.x;
    const int b   = blockIdx.x;

    if (b < 8) {
        int j = b * 512 + tid;
        float4 s = state[j];
        ((float2*)g_pos4)[j] = make_float2(s.x, s.y);
        return;
    }

    // ---- Robot row-0 force over all 4096 pairs (8 iters/thread) ----
    __shared__ float2 wsum[16];
    const float4 s0 = state[0];
    float fx = 0.0f, fy = 0.0f;
    #pragma unroll
    for (int k = 0; k < NN / 512; k++) {
        float4 q  = state[tid + k * 512];
        float dx  = s0.x - q.x;
        float dy  = s0.y - q.y;
        float s2  = fmaf(dx, dx, fmaf(dy, dy, EPSF));
        float rin = rsqrt_approx(s2);
        float m   = ex2_approx(fmaf(s2 * rin, C1C, C0C));
        float f   = m * rin;
        fx = fmaf(f, dx, fx);
        fy = fmaf(f, dy, fy);
    }
    #pragma unroll
    for (int sh = 16; sh > 0; sh >>= 1) {
        fx += __shfl_xor_sync(0xffffffffu, fx, sh);
        fy += __shfl_xor_sync(0xffffffffu, fy, sh);
    }
    if ((tid & 31) == 0) wsum[tid >> 5] = make_float2(fx, fy);
    __syncthreads();

    if (tid == 0) {
        float rx = 0.0f, ry = 0.0f;
        #pragma unroll
        for (int w = 0; w < 16; w++) { rx += wsum[w].x; ry += wsum[w].y; }
        rx *= ALPHA;
        ry *= ALPHA;

        float2 g0  = goals[0];
        float tgx  = g0.x - s0.x;
        float tgy  = g0.y - s0.y;
        float dist = sqrtf(fmaf(tgx, tgx, tgy * tgy));
        float einv = 1.0f / (dist + EPSF);
        float Fx   = rx + K_ATTR * (ROBOT_SPEED * tgx * einv - s0.z) * PED_MASS;
        float Fy   = ry + K_ATTR * (ROBOT_SPEED * tgy * einv - s0.w) * PED_MASS;

        float vnx   = fmaf(Fx, DT / PED_MASS, s0.z);
        float vny   = fmaf(Fy, DT / PED_MASS, s0.w);
        float speed = sqrtf(fmaf(vnx, vnx, vny * vny));
        float sc    = fminf(1.0f, PED_SPEED / (speed + EPSF));
        vnx *= sc;
        vny *= sc;
        float r0x = fmaf(vnx, DT, s0.x);
        float r0y = fmaf(vny, DT, s0.y);

        float rix = robot_init[0];
        float riy = robot_init[1];
        float gx  = g0.x - rix;
        float gy  = g0.y - riy;
        float PG  = (gx * (r0x - rix) + gy * (r0y - riy)) /
                    (sqrtf(fmaf(gx, gx, gy * gy)) + E_COST);
        g_robo[0] = r0x;
        g_robo[1] = r0y;
        g_robo[2] = PG;
    }
}

// Main: 1024 blocks x 128 threads; one warp per row (4096 warps total, all
// resident, ~1% balance quantization). Positions streamed from L1 via LDG.128.
__global__ void __launch_bounds__(128) force_kernel(
    const float4* __restrict__ state,
    const float*  __restrict__ cost_in,
    const float4* __restrict__ stacked_in,
    const float2* __restrict__ goals,
    float4* __restrict__ out_state,
    float*  __restrict__ out_cost,
    float4* __restrict__ out_stacked)
{
    const int tid  = threadIdx.x;
    const int b    = blockIdx.x;
    const int row  = b * 4 + (tid >> 5);
    const int lane = tid & 31;

    // Stacked output copy for this block's 4 rows
    if (tid < 4) {
        int r = b * 4 + tid;
        out_stacked[r] = stacked_in[r];
    } else if (tid < 8) {
        int r = b * 4 + (tid - 4);
        out_stacked[NN + r] = state[r];
    }

    const float4 st = state[row];  // warp-uniform -> broadcast
    const float px = st.x, py = st.y;

    float fxa = 0.0f, fya = 0.0f;  // two independent accumulator chains
    float fxb = 0.0f, fyb = 0.0f;

    // 64 counted iters, 2 pairs per LDG.128 (L1-resident 32KB array).
    // Self-pair contributes exactly 0 (dx=dy=0, f finite via EPS).
    #pragma unroll 8
    for (int k = 0; k < NN / 64; k++) {
        float4 q = g_pos4[lane + k * 32];

        float dx0  = px - q.x;
        float dy0  = py - q.y;
        float s20  = fmaf(dx0, dx0, fmaf(dy0, dy0, EPSF));
        float rin0 = rsqrt_approx(s20);
        float m0   = ex2_approx(fmaf(s20 * rin0, C1C, C0C));
        float f0   = m0 * rin0;
        fxa = fmaf(f0, dx0, fxa);
        fya = fmaf(f0, dy0, fya);

        float dx1  = px - q.z;
        float dy1  = py - q.w;
        float s21  = fmaf(dx1, dx1, fmaf(dy1, dy1, EPSF));
        float rin1 = rsqrt_approx(s21);
        float m1   = ex2_approx(fmaf(s21 * rin1, C1C, C0C));
        float f1   = m1 * rin1;
        fxb = fmaf(f1, dx1, fxb);
        fyb = fmaf(f1, dy1, fyb);
    }
    float fx = fxa + fxb;
    float fy = fya + fyb;

    #pragma unroll
    for (int sh = 16; sh > 0; sh >>= 1) {
        fx += __shfl_xor_sync(0xffffffffu, fx, sh);
        fy += __shfl_xor_sync(0xffffffffu, fy, sh);
    }

    // Lane 0: attraction + pose propagation + cost for own row
    if (lane == 0) {
        fx *= ALPHA;
        fy *= ALPHA;

        float2 g   = goals[row];
        float tgx  = g.x - px;
        float tgy  = g.y - py;
        float dist = sqrtf(fmaf(tgx, tgx, tgy * tgy));
        float einv = 1.0f / (dist + EPSF);
        float ds   = (row == 0) ? ROBOT_SPEED : PED_SPEED;
        float Fx   = fx + K_ATTR * (ds * tgx * einv - st.z) * PED_MASS;
        float Fy   = fy + K_ATTR * (ds * tgy * einv - st.w) * PED_MASS;

        float vnx   = fmaf(Fx, DT / PED_MASS, st.z);
        float vny   = fmaf(Fy, DT / PED_MASS, st.w);
        float speed = sqrtf(fmaf(vnx, vnx, vny * vny));
        float sc    = fminf(1.0f, PED_SPEED / (speed + EPSF));
        vnx *= sc;
        vny *= sc;
        float pnx = fmaf(vnx, DT, px);
        float pny = fmaf(vny, DT, py);
        out_state[row] = make_float4(pnx, pny, vnx, vny);

        // Cost (robot pose + PG precomputed by prep kernel)
        float r0x = g_robo[0], r0y = g_robo[1], PG = g_robo[2];
        float ddx = pnx - r0x;
        float ddy = pny - r0y;
        float dr  = sqrtf(fmaf(ddx, ddx, fmaf(ddy, ddy, E_COST)));
        float blame = (row == 0) ? 0.0f : ex2_approx(-dr * (LOG2E / B_COST));
        out_cost[row] = cost_in[row] + (-A_COST * PG + blame);
    }
}

extern "C" void kernel_launch(void* const* d_in, const int* in_sizes, int n_in,
                              void* d_out, int out_size)
{
    const float4* state   = (const float4*)d_in[0];
    const float*  cost    = (const float*)d_in[1];
    const float4* stacked = (const float4*)d_in[2];
    const float2* goals   = (const float2*)d_in[3];
    const float*  rinit   = (const float*)d_in[4];

    float*  out         = (float*)d_out;
    float4* out_state   = (float4*)out;            // [0, 4N)
    float*  out_cost    = out + 4 * NN;            // [4N, 5N)
    float4* out_stacked = (float4*)(out + 5 * NN); // [5N, 13N)

    prep_kernel<<<9, 512>>>(state, goals, rinit);
    force_kernel<<<NN / 4, 128>>>(state, cost, stacked, goals,
                                  out_state, out_cost, out_stacked);
}